// round 4
// baseline (speedup 1.0000x reference)
#include <cuda_runtime.h>

// BKT_RNN: T=1024 timesteps, B=4096 independent chains, H=4 hidden.
// Round 3: TWO chains per thread (pure ILP), scalar math, fused loss.
// 64 blocks x 32 threads = 2048 threads; thread handles chains b and b+2048.
//
// Math (exact up to fp rounding):
//  1) BKT m_t == latent identically, so latent' = latent*((1-f)-l) + l,
//     correct = latent*((1-s)-g) + g, with l=1-r0, f=1-r1, g=1-r2, s=1-r3.
//  2) r-form tanh: h = 1-2r, r = 1/(exp(2z)+1); params p_j = 1-r_j, with
//     pre-scaled weights W' = -4*log2e*W_hh, bias shifted by row sums.

#define Tn 1024
#define Bn 4096
#define NBLK 64
#define NTHR 32
#define CSTRIDE 2048   // second chain offset

__device__ float    g_part[NBLK];
__device__ unsigned g_ctr = 0;

__device__ __forceinline__ float ex2_f(float a){ float r; asm("ex2.approx.f32 %0, %1;" : "=f"(r) : "f"(a)); return r; }
__device__ __forceinline__ float rcp_f(float a){ float r; asm("rcp.approx.f32 %0, %1;" : "=f"(r) : "f"(a)); return r; }
__device__ __forceinline__ float lg2_f(float a){ float r; asm("lg2.approx.f32 %0, %1;" : "=f"(r) : "f"(a)); return r; }

struct Chain {
    float r0, r1, r2, r3;   // r = (1-h)/2
    float latent;
    float lacc;
};

__global__ __launch_bounds__(NTHR, 1) void bkt_main(
    const float* __restrict__ x, const float* __restrict__ y,
    const float* __restrict__ prior,
    const float* __restrict__ W_ih, const float* __restrict__ W_hh,
    const float* __restrict__ b_ih, const float* __restrict__ b_hh,
    float* __restrict__ out)
{
    const int b0 = blockIdx.x * NTHR + threadIdx.x;
    const int b1 = b0 + CSTRIDE;
    const float L2E2 = 2.8853900817779268f;   // 2*log2(e)

    // Pre-scaled weights (broadcast loads, amortized over 1024 steps)
    float C0[4], Cx[4], Wp[4][4];
    #pragma unroll
    for (int j = 0; j < 4; j++) {
        float S = 0.f;
        #pragma unroll
        for (int k = 0; k < 4; k++) {
            float w = W_hh[j * 4 + k];
            Wp[j][k] = -2.f * L2E2 * w;      // -4*log2e*W  (matvec over r)
            S += w;
        }
        C0[j] = L2E2 * (b_ih[j] + b_hh[j] + S);
        Cx[j] = L2E2 * W_ih[j];
    }

    // latent0 = sigmoid(prior)
    const float pz = prior[0];
    const float lat0 = 1.f / (1.f + ex2_f(-pz * 1.4426950408889634f));

    Chain A, B;
    A.r0 = A.r1 = A.r2 = A.r3 = 0.5f; A.latent = lat0; A.lacc = 0.f;
    B.r0 = B.r1 = B.r2 = B.r3 = 0.5f; B.latent = lat0; B.lacc = 0.f;

    const float* xp0 = x + b0; const float* yp0 = y + b0;
    const float* xp1 = x + b1; const float* yp1 = y + b1;
    float* __restrict__ oc0 = out + b0;
    float* __restrict__ ol0 = out + (size_t)Tn * Bn + b0;
    float* __restrict__ oc1 = out + b1;
    float* __restrict__ ol1 = out + (size_t)Tn * Bn + b1;

    // One RNN+BKT step for one chain. Two independent dependency chains per
    // call (r-recurrence and latent-recurrence); two calls (A,B) interleave.
    auto step = [&](Chain& c, float xv, float yv, float* ocp, float* olp, size_t row) {
        // matvec in r-domain
        float u0 = fmaf(xv, Cx[0], C0[0]);
        float u1 = fmaf(xv, Cx[1], C0[1]);
        float u2 = fmaf(xv, Cx[2], C0[2]);
        float u3 = fmaf(xv, Cx[3], C0[3]);
        u0 = fmaf(c.r0, Wp[0][0], u0); u1 = fmaf(c.r0, Wp[1][0], u1);
        u2 = fmaf(c.r0, Wp[2][0], u2); u3 = fmaf(c.r0, Wp[3][0], u3);
        u0 = fmaf(c.r1, Wp[0][1], u0); u1 = fmaf(c.r1, Wp[1][1], u1);
        u2 = fmaf(c.r1, Wp[2][1], u2); u3 = fmaf(c.r1, Wp[3][1], u3);
        u0 = fmaf(c.r2, Wp[0][2], u0); u1 = fmaf(c.r2, Wp[1][2], u1);
        u2 = fmaf(c.r2, Wp[2][2], u2); u3 = fmaf(c.r2, Wp[3][2], u3);
        u0 = fmaf(c.r3, Wp[0][3], u0); u1 = fmaf(c.r3, Wp[1][3], u1);
        u2 = fmaf(c.r3, Wp[2][3], u2); u3 = fmaf(c.r3, Wp[3][3], u3);
        float E0 = ex2_f(u0), E1 = ex2_f(u1), E2 = ex2_f(u2), E3 = ex2_f(u3);

        // BKT with the CURRENT step's r (needs fresh r) — but the latent
        // recurrence itself is only 2 FMAs deep, so it stays off the long path.
        float nr0 = rcp_f(E0 + 1.f);
        float nr1 = rcp_f(E1 + 1.f);
        float nr2 = rcp_f(E2 + 1.f);
        float nr3 = rcp_f(E3 + 1.f);

        float Ac = (nr3 + nr2) - 1.f;               // (1-s) - g
        float g  = 1.f - nr2;
        float correct = fmaf(c.latent, Ac, g);
        float omc     = fmaf(-c.latent, Ac, nr2);   // 1 - correct
        float Al = (nr1 + nr0) - 1.f;               // (1-f) - l
        float l  = 1.f - nr0;
        float latn = fmaf(c.latent, Al, l);

        float pe = fmaf(yv, correct - omc, omc);
        float ll = fmaxf(lg2_f(pe) * 0.69314718055994531f, -100.f);
        c.lacc += ll;

        ocp[row] = correct;
        olp[row] = latn;

        c.r0 = nr0; c.r1 = nr1; c.r2 = nr2; c.r3 = nr3;
        c.latent = latn;
    };

    // Rolling 8-deep prefetch buffers (both chains)
    float bx0[8], by0[8], bx1[8], by1[8];
    #pragma unroll
    for (int u = 0; u < 8; u++) {
        bx0[u] = xp0[u * Bn]; by0[u] = yp0[u * Bn];
        bx1[u] = xp1[u * Bn]; by1[u] = yp1[u * Bn];
    }

    // One 8-step group; Prefetch is compile-time.
    auto group = [&](int t0, bool prefetch) {
        #pragma unroll
        for (int u = 0; u < 8; u++) {
            const size_t row = (size_t)(t0 + u) * Bn;
            float xa = bx0[u], ya = by0[u];
            float xb = bx1[u], yb = by1[u];
            if (prefetch) {
                const size_t prow = row + (size_t)8 * Bn;
                bx0[u] = xp0[prow]; by0[u] = yp0[prow];
                bx1[u] = xp1[prow]; by1[u] = yp1[prow];
            }
            step(A, xa, ya, oc0, ol0, row);
            step(B, xb, yb, oc1, ol1, row);
        }
    };

    #pragma unroll 1
    for (int t0 = 0; t0 < Tn - 8; t0 += 8) group(t0, true);
    group(Tn - 8, false);

    // Deterministic loss: warp reduce -> per-block partial -> last block sums
    float lacc = A.lacc + B.lacc;
    #pragma unroll
    for (int o = 16; o; o >>= 1) lacc += __shfl_xor_sync(0xffffffffu, lacc, o);

    __shared__ unsigned sLast;
    if (threadIdx.x == 0) {
        g_part[blockIdx.x] = lacc;
        __threadfence();
        unsigned ticket = atomicAdd(&g_ctr, 1u);
        sLast = (ticket == NBLK - 1) ? 1u : 0u;
    }
    __syncthreads();
    if (sLast) {
        __threadfence();  // acquire: make all g_part writes visible
        int tid = threadIdx.x;
        float v = g_part[tid] + g_part[tid + 32];
        #pragma unroll
        for (int o = 16; o; o >>= 1) v += __shfl_xor_sync(0xffffffffu, v, o);
        if (tid == 0) {
            out[(size_t)2 * Tn * Bn] = -v / (float)((size_t)Tn * Bn);
            __threadfence();
            g_ctr = 0;   // reset for next graph replay
        }
    }
}

extern "C" void kernel_launch(void* const* d_in, const int* in_sizes, int n_in,
                              void* d_out, int out_size)
{
    (void)in_sizes; (void)n_in; (void)out_size;
    const float* x     = (const float*)d_in[0];
    const float* y     = (const float*)d_in[1];
    const float* prior = (const float*)d_in[2];
    const float* W_ih  = (const float*)d_in[3];
    const float* W_hh  = (const float*)d_in[4];
    const float* b_ih  = (const float*)d_in[5];
    const float* b_hh  = (const float*)d_in[6];
    float* out = (float*)d_out;

    bkt_main<<<NBLK, NTHR>>>(x, y, prior, W_ih, W_hh, b_ih, b_hh, out);
}

// round 5
// speedup vs baseline: 2.4579x; 2.4579x over previous
#include <cuda_runtime.h>

// BKT_RNN: T=1024 timesteps, B=4096 independent chains, H=4 hidden.
// Round 4: back to 128 blocks x 32 threads (all SMs), tanh.approx (1 MUFU per
// unit instead of ex2+rcp), binary-input FSELs off the fma pipe, deferred ln2.
//
// Math (exact up to fp rounding):
//  1) BKT m_t == latent identically, so latent' = latent*((1-f)-l) + l,
//     correct = latent*((1-s)-g) + g, with params (l,f,g,s) = (h+1)/2.
//     => correct = (h2+1)/2 - 0.5*latent*(h2+h3)
//        latent' = (h0+1)/2 - 0.5*latent*(h0+h1)
//  2) x,y in {0,1}: bias term selected (C0 vs C1), BCE pe selected.
//  3) loss accumulated in log2 units, clamped at -100/ln2, scaled once.

#define Tn 1024
#define Bn 4096
#define NBLK 128
#define NTHR 32

__device__ float    g_part[NBLK];
__device__ unsigned g_ctr = 0;

__device__ __forceinline__ float tanh_f(float a){ float r; asm("tanh.approx.f32 %0, %1;" : "=f"(r) : "f"(a)); return r; }
__device__ __forceinline__ float ex2_f(float a){ float r; asm("ex2.approx.f32 %0, %1;" : "=f"(r) : "f"(a)); return r; }
__device__ __forceinline__ float lg2_f(float a){ float r; asm("lg2.approx.f32 %0, %1;" : "=f"(r) : "f"(a)); return r; }

__global__ __launch_bounds__(NTHR, 1) void bkt_main(
    const float* __restrict__ x, const float* __restrict__ y,
    const float* __restrict__ prior,
    const float* __restrict__ W_ih, const float* __restrict__ W_hh,
    const float* __restrict__ b_ih, const float* __restrict__ b_hh,
    float* __restrict__ out)
{
    const int b = blockIdx.x * NTHR + threadIdx.x;

    // Bias for x=0 and x=1 (x is binary), raw W_hh for the h-matvec.
    float C0[4], C1[4], W[4][4];
    #pragma unroll
    for (int j = 0; j < 4; j++) {
        #pragma unroll
        for (int k = 0; k < 4; k++) W[j][k] = W_hh[j * 4 + k];
        float base = b_ih[j] + b_hh[j];
        C0[j] = base;
        C1[j] = base + W_ih[j];
    }

    // latent0 = sigmoid(prior)
    const float pz = prior[0];
    float latent = 1.f / (1.f + ex2_f(-pz * 1.4426950408889634f));

    const float* xp = x + b;
    const float* yp = y + b;
    float* __restrict__ oc = out + b;                    // corrects [0, T*B)
    float* __restrict__ ol = out + (size_t)Tn * Bn + b;  // latents  [T*B, 2*T*B)

    float h0 = 0.f, h1 = 0.f, h2 = 0.f, h3 = 0.f;
    float lacc = 0.f;
    const float CLAMP2 = -144.26950408889634f;           // -100 / ln(2)

    auto step = [&](float xv, float yv, size_t row) {
        // RNN: u_j = bias(x) + sum_k W[j][k]*h_k ; h'_j = tanh(u_j)
        bool px = (xv != 0.f);
        float u0 = px ? C1[0] : C0[0];
        float u1 = px ? C1[1] : C0[1];
        float u2 = px ? C1[2] : C0[2];
        float u3 = px ? C1[3] : C0[3];
        u0 = fmaf(h0, W[0][0], u0); u1 = fmaf(h0, W[1][0], u1);
        u2 = fmaf(h0, W[2][0], u2); u3 = fmaf(h0, W[3][0], u3);
        u0 = fmaf(h1, W[0][1], u0); u1 = fmaf(h1, W[1][1], u1);
        u2 = fmaf(h1, W[2][1], u2); u3 = fmaf(h1, W[3][1], u3);
        u0 = fmaf(h2, W[0][2], u0); u1 = fmaf(h2, W[1][2], u1);
        u2 = fmaf(h2, W[2][2], u2); u3 = fmaf(h2, W[3][2], u3);
        u0 = fmaf(h3, W[0][3], u0); u1 = fmaf(h3, W[1][3], u1);
        u2 = fmaf(h3, W[2][3], u2); u3 = fmaf(h3, W[3][3], u3);
        h0 = tanh_f(u0); h1 = tanh_f(u1); h2 = tanh_f(u2); h3 = tanh_f(u3);

        // BKT: correct = (h2+1)/2 - 0.5*latent*(h2+h3)
        //      latent' = (h0+1)/2 - 0.5*latent*(h0+h1)
        float nhl = -0.5f * latent;
        float sA  = h2 + h3;
        float g5  = fmaf(h2, 0.5f, 0.5f);
        float correct = fmaf(nhl, sA, g5);
        float omc = 1.f - correct;
        float sB  = h0 + h1;
        float l5  = fmaf(h0, 0.5f, 0.5f);
        float latn = fmaf(nhl, sB, l5);

        // BCE in log2 units (y binary -> select)
        float pe = (yv != 0.f) ? correct : omc;
        lacc += fmaxf(lg2_f(pe), CLAMP2);

        oc[row] = correct;
        ol[row] = latn;
        latent = latn;
    };

    // Rolling 8-deep prefetch
    float bx[8], by[8];
    #pragma unroll
    for (int u = 0; u < 8; u++) { bx[u] = xp[u * Bn]; by[u] = yp[u * Bn]; }

    #pragma unroll 1
    for (int t0 = 0; t0 < Tn - 8; t0 += 8) {
        #pragma unroll
        for (int u = 0; u < 8; u++) {
            const size_t row = (size_t)(t0 + u) * Bn;
            float xa = bx[u], ya = by[u];
            const size_t prow = row + (size_t)8 * Bn;
            bx[u] = xp[prow]; by[u] = yp[prow];
            step(xa, ya, row);
        }
    }
    #pragma unroll
    for (int u = 0; u < 8; u++) {
        const size_t row = (size_t)(Tn - 8 + u) * Bn;
        step(bx[u], by[u], row);
    }

    // Deterministic loss: warp reduce -> per-block partial -> last block sums
    lacc *= 0.69314718055994531f;   // back to natural log
    #pragma unroll
    for (int o = 16; o; o >>= 1) lacc += __shfl_xor_sync(0xffffffffu, lacc, o);

    __shared__ unsigned sLast;
    if (threadIdx.x == 0) {
        g_part[blockIdx.x] = lacc;
        __threadfence();
        unsigned ticket = atomicAdd(&g_ctr, 1u);
        sLast = (ticket == NBLK - 1) ? 1u : 0u;
    }
    __syncthreads();
    if (sLast) {
        __threadfence();  // acquire: make all g_part writes visible
        int tid = threadIdx.x;
        float v = g_part[tid] + g_part[tid + 32] + g_part[tid + 64] + g_part[tid + 96];
        #pragma unroll
        for (int o = 16; o; o >>= 1) v += __shfl_xor_sync(0xffffffffu, v, o);
        if (tid == 0) {
            out[(size_t)2 * Tn * Bn] = -v / (float)((size_t)Tn * Bn);
            __threadfence();
            g_ctr = 0;   // reset for next graph replay
        }
    }
}

extern "C" void kernel_launch(void* const* d_in, const int* in_sizes, int n_in,
                              void* d_out, int out_size)
{
    (void)in_sizes; (void)n_in; (void)out_size;
    const float* x     = (const float*)d_in[0];
    const float* y     = (const float*)d_in[1];
    const float* prior = (const float*)d_in[2];
    const float* W_ih  = (const float*)d_in[3];
    const float* W_hh  = (const float*)d_in[4];
    const float* b_ih  = (const float*)d_in[5];
    const float* b_hh  = (const float*)d_in[6];
    float* out = (float*)d_out;

    bkt_main<<<NBLK, NTHR>>>(x, y, prior, W_ih, W_hh, b_ih, b_hh, out);
}